// round 1
// baseline (speedup 1.0000x reference)
#include <cuda_runtime.h>

#define NN   100000
#define EE   3200000
#define FH   256
#define FIN  512
#define FOUT 64
#define HOPS 10

// ---------------- scratch (device globals: no allocations allowed) ----------
__device__ float g_x0 [(size_t)NN * FH];
__device__ float g_tmp[(size_t)NN * FH];
__device__ float g_hA [(size_t)NN * FH];
__device__ float g_hB [(size_t)NN * FH];
__device__ int   g_rowstart[NN + 1];
__device__ int   g_cnt[NN];
__device__ int   g_scol[EE];
__device__ float g_sval[EE];

// ---------------- CSR build ------------------------------------------------
__global__ void zero_cnt_kernel() {
    int i = blockIdx.x * blockDim.x + threadIdx.x;
    if (i < NN) g_cnt[i] = 0;
}

__global__ void hist_kernel(const int* __restrict__ erow) {
    int e = blockIdx.x * blockDim.x + threadIdx.x;
    if (e < EE) atomicAdd(&g_cnt[erow[e]], 1);
}

// single-block exclusive scan of g_cnt[0..NN) -> g_rowstart
__global__ void scan_kernel() {
    __shared__ int s[1024];
    __shared__ int carry_s;
    int t = threadIdx.x;
    if (t == 0) carry_s = 0;
    __syncthreads();
    for (int base = 0; base < NN; base += 1024) {
        int i = base + t;
        int v = (i < NN) ? g_cnt[i] : 0;
        s[t] = v;
        __syncthreads();
        #pragma unroll
        for (int off = 1; off < 1024; off <<= 1) {
            int add = (t >= off) ? s[t - off] : 0;
            __syncthreads();
            s[t] += add;
            __syncthreads();
        }
        if (i < NN) g_rowstart[i] = carry_s + s[t] - v;   // exclusive
        __syncthreads();
        if (t == 1023) carry_s += s[1023];
        __syncthreads();
    }
    if (t == 0) g_rowstart[NN] = carry_s;
}

__global__ void scatter_kernel(const int* __restrict__ erow,
                               const int* __restrict__ ecol,
                               const float* __restrict__ eval) {
    int e = blockIdx.x * blockDim.x + threadIdx.x;
    if (e < EE) {
        int r = erow[e];
        int p = g_rowstart[r] + atomicAdd(&g_cnt[r], 1);
        g_scol[p] = ecol[e];
        g_sval[p] = eval[e];
    }
}

// ---------------- SPMM: g_tmp[row,:] = sum_e val*h[col,:] + A2[row]*x0[row,:]
// 64 threads per row (float4 per thread), 4 rows per 256-thread block.
__global__ void spmm_kernel(const float* __restrict__ h,
                            const float* __restrict__ A2) {
    int row = blockIdx.x * 4 + (threadIdx.x >> 6);
    int f4  = threadIdx.x & 63;
    if (row >= NN) return;
    int s = g_rowstart[row];
    int e = g_rowstart[row + 1];
    float4 acc = make_float4(0.f, 0.f, 0.f, 0.f);
    #pragma unroll 4
    for (int p = s; p < e; ++p) {
        int   c = __ldg(&g_scol[p]);
        float v = __ldg(&g_sval[p]);
        float4 hv = __ldg(((const float4*)(h + (size_t)c * FH)) + f4);
        acc.x += v * hv.x;
        acc.y += v * hv.y;
        acc.z += v * hv.z;
        acc.w += v * hv.w;
    }
    float a = __ldg(&A2[row]);
    float4 xv = __ldg(((const float4*)(g_x0 + (size_t)row * FH)) + f4);
    acc.x += a * xv.x;
    acc.y += a * xv.y;
    acc.z += a * xv.z;
    acc.w += a * xv.w;
    ((float4*)(g_tmp + (size_t)row * FH))[f4] = acc;
}

// ---------------- tiled fp32 GEMM: C = epilogue(A[M,K] @ B[K,Nc]) -----------
// MODE 0: relu(acc + bias)        (x -> x0)
// MODE 1: relu(acc + bias + Cadd) (hop update, Cadd = tmp)
// MODE 2: acc + bias              (final projection)
template <int MODE>
__global__ __launch_bounds__(256, 2)
void gemm128_kernel(const float* __restrict__ A, const float* __restrict__ B,
                    const float* __restrict__ bias, const float* __restrict__ Cadd,
                    float* __restrict__ C, int M, int K, int Nc) {
    __shared__ float As[16][132];   // transposed A tile, padded
    __shared__ float Bs[16][128];

    int tid = threadIdx.x;
    int tx = tid & 15;       // 0..15  -> 8 cols each
    int ty = tid >> 4;       // 0..15  -> 8 rows each
    int m0 = blockIdx.y * 128;
    int n0 = blockIdx.x * 128;

    float acc[8][8];
    #pragma unroll
    for (int i = 0; i < 8; i++)
        #pragma unroll
        for (int j = 0; j < 8; j++) acc[i][j] = 0.f;

    for (int k0 = 0; k0 < K; k0 += 16) {
        // load A tile (128 rows x 16 k), store transposed
        #pragma unroll
        for (int i = 0; i < 2; i++) {
            int id = tid + i * 256;       // 0..511
            int r  = id >> 2;             // 0..127
            int g  = id & 3;              // 0..3 (float4 group)
            int gm = m0 + r;
            float4 av = make_float4(0.f, 0.f, 0.f, 0.f);
            if (gm < M)
                av = *(const float4*)(A + (size_t)gm * K + k0 + g * 4);
            As[g * 4 + 0][r] = av.x;
            As[g * 4 + 1][r] = av.y;
            As[g * 4 + 2][r] = av.z;
            As[g * 4 + 3][r] = av.w;
        }
        // load B tile (16 k x 128 cols)
        #pragma unroll
        for (int i = 0; i < 2; i++) {
            int id = tid + i * 256;       // 0..511
            int rb = id >> 5;             // 0..15
            int cb = id & 31;             // 0..31 (float4 group)
            int gn = n0 + cb * 4;
            float4 bv = make_float4(0.f, 0.f, 0.f, 0.f);
            if (gn < Nc)
                bv = *(const float4*)(B + (size_t)(k0 + rb) * Nc + gn);
            *(float4*)&Bs[rb][cb * 4] = bv;
        }
        __syncthreads();

        #pragma unroll
        for (int k = 0; k < 16; k++) {
            float4 a0 = *(const float4*)&As[k][ty * 8];
            float4 a1 = *(const float4*)&As[k][ty * 8 + 4];
            float4 b0 = *(const float4*)&Bs[k][tx * 8];
            float4 b1 = *(const float4*)&Bs[k][tx * 8 + 4];
            float av[8] = {a0.x, a0.y, a0.z, a0.w, a1.x, a1.y, a1.z, a1.w};
            float bv[8] = {b0.x, b0.y, b0.z, b0.w, b1.x, b1.y, b1.z, b1.w};
            #pragma unroll
            for (int i = 0; i < 8; i++)
                #pragma unroll
                for (int j = 0; j < 8; j++)
                    acc[i][j] += av[i] * bv[j];
        }
        __syncthreads();
    }

    // epilogue
    #pragma unroll
    for (int i = 0; i < 8; i++) {
        int m = m0 + ty * 8 + i;
        if (m >= M) continue;
        #pragma unroll
        for (int j = 0; j < 8; j++) {
            int n = n0 + tx * 8 + j;
            if (n >= Nc) continue;
            float v = acc[i][j] + __ldg(&bias[n]);
            if (MODE == 1) v += __ldg(&Cadd[(size_t)m * Nc + n]);
            if (MODE != 2) v = fmaxf(v, 0.f);
            C[(size_t)m * Nc + n] = v;
        }
    }
}

// ---------------- launch ----------------------------------------------------
extern "C" void kernel_launch(void* const* d_in, const int* in_sizes, int n_in,
                              void* d_out, int out_size) {
    const float* x    = (const float*)d_in[0];
    const int*   erow = (const int*)  d_in[1];
    const int*   ecol = (const int*)  d_in[2];
    const float* eval = (const float*)d_in[3];
    const float* A2   = (const float*)d_in[4];
    const float* W1   = (const float*)d_in[5];
    const float* b1   = (const float*)d_in[6];
    const float* W3   = (const float*)d_in[7];
    const float* b3   = (const float*)d_in[8];
    const float* W2   = (const float*)d_in[9];
    const float* b2   = (const float*)d_in[10];
    float* out = (float*)d_out;

    float *px0, *ptmp, *phA, *phB;
    cudaGetSymbolAddress((void**)&px0, g_x0);
    cudaGetSymbolAddress((void**)&ptmp, g_tmp);
    cudaGetSymbolAddress((void**)&phA, g_hA);
    cudaGetSymbolAddress((void**)&phB, g_hB);

    // ---- CSR build ----
    zero_cnt_kernel<<<(NN + 255) / 256, 256>>>();
    hist_kernel<<<(EE + 255) / 256, 256>>>(erow);
    scan_kernel<<<1, 1024>>>();
    zero_cnt_kernel<<<(NN + 255) / 256, 256>>>();
    scatter_kernel<<<(EE + 255) / 256, 256>>>(erow, ecol, eval);

    // ---- x0 = relu(x @ W1 + b1) ----
    dim3 grid1((FH + 127) / 128, (NN + 127) / 128);
    gemm128_kernel<0><<<grid1, 256>>>(x, W1, b1, nullptr, px0, NN, FIN, FH);

    // ---- 10 hops ----
    const float* h = px0;
    float* bufs[2] = {phA, phB};
    for (int i = 0; i < HOPS; i++) {
        spmm_kernel<<<(NN + 3) / 4, 256>>>(h, A2);
        float* hn = bufs[i & 1];
        dim3 grid3((FH + 127) / 128, (NN + 127) / 128);
        gemm128_kernel<1><<<grid3, 256>>>(ptmp, W3, b3, ptmp, hn, NN, FH, FH);
        h = hn;
    }

    // ---- out = h @ W2 + b2 ----
    dim3 grid2((FOUT + 127) / 128, (NN + 127) / 128);
    gemm128_kernel<2><<<grid2, 256>>>(h, W2, b2, nullptr, out, NN, FH, FOUT);
}

// round 2
// speedup vs baseline: 1.5019x; 1.5019x over previous
#include <cuda_runtime.h>
#include <cstdint>

#define NN   100000
#define EE   3200000
#define FH   256
#define FIN  512
#define FOUT 64
#define HOPS 10

// ---------------- scratch (device globals: no allocations allowed) ----------
__device__ float g_x0 [(size_t)NN * FH];
__device__ float g_tmp[(size_t)NN * FH];
__device__ float g_hA [(size_t)NN * FH];
__device__ float g_hB [(size_t)NN * FH];
__device__ int   g_rowstart[NN + 1];
__device__ int   g_cnt[NN];
__device__ int   g_scol[EE];
__device__ float g_sval[EE];

// ---------------- CSR build ------------------------------------------------
__global__ void zero_cnt_kernel() {
    int i = blockIdx.x * blockDim.x + threadIdx.x;
    if (i < NN) g_cnt[i] = 0;
}

__global__ void hist_kernel(const int* __restrict__ erow) {
    int e = blockIdx.x * blockDim.x + threadIdx.x;
    if (e < EE) atomicAdd(&g_cnt[erow[e]], 1);
}

// single-block exclusive scan of g_cnt[0..NN) -> g_rowstart
__global__ void scan_kernel() {
    __shared__ int s[1024];
    __shared__ int carry_s;
    int t = threadIdx.x;
    if (t == 0) carry_s = 0;
    __syncthreads();
    for (int base = 0; base < NN; base += 1024) {
        int i = base + t;
        int v = (i < NN) ? g_cnt[i] : 0;
        s[t] = v;
        __syncthreads();
        #pragma unroll
        for (int off = 1; off < 1024; off <<= 1) {
            int add = (t >= off) ? s[t - off] : 0;
            __syncthreads();
            s[t] += add;
            __syncthreads();
        }
        if (i < NN) g_rowstart[i] = carry_s + s[t] - v;   // exclusive
        __syncthreads();
        if (t == 1023) carry_s += s[1023];
        __syncthreads();
    }
    if (t == 0) g_rowstart[NN] = carry_s;
}

__global__ void scatter_kernel(const int* __restrict__ erow,
                               const int* __restrict__ ecol,
                               const float* __restrict__ eval) {
    int e = blockIdx.x * blockDim.x + threadIdx.x;
    if (e < EE) {
        int r = erow[e];
        int p = g_rowstart[r] + atomicAdd(&g_cnt[r], 1);
        g_scol[p] = ecol[e];
        g_sval[p] = eval[e];
    }
}

// ---------------- SPMM: g_tmp[row,:] = sum_e val*h[col,:] + A2[row]*x0[row,:]
__global__ void spmm_kernel(const float* __restrict__ h,
                            const float* __restrict__ A2) {
    int row = blockIdx.x * 4 + (threadIdx.x >> 6);
    int f4  = threadIdx.x & 63;
    if (row >= NN) return;
    int s = g_rowstart[row];
    int e = g_rowstart[row + 1];
    float4 acc = make_float4(0.f, 0.f, 0.f, 0.f);
    #pragma unroll 4
    for (int p = s; p < e; ++p) {
        int   c = __ldg(&g_scol[p]);
        float v = __ldg(&g_sval[p]);
        float4 hv = __ldg(((const float4*)(h + (size_t)c * FH)) + f4);
        acc.x += v * hv.x;
        acc.y += v * hv.y;
        acc.z += v * hv.z;
        acc.w += v * hv.w;
    }
    float a = __ldg(&A2[row]);
    float4 xv = __ldg(((const float4*)(g_x0 + (size_t)row * FH)) + f4);
    acc.x += a * xv.x;
    acc.y += a * xv.y;
    acc.z += a * xv.z;
    acc.w += a * xv.w;
    ((float4*)(g_tmp + (size_t)row * FH))[f4] = acc;
}

// ---------------- tf32 tensor-core GEMM ------------------------------------
// C[M,Nc] = epilogue(A[M,K] @ B[K,Nc])
// MODE 0: relu(acc + bias)         MODE 1: relu(acc + bias + Cadd)
// MODE 2: acc + bias
// CTA tile 128x128, BK=32. 8 warps: warp_m = wid%4 (32 rows), warp_n = wid/4 (64 cols).

__device__ __forceinline__ float f2tf32(float x) {
    uint32_t u;
    asm("cvt.rna.tf32.f32 %0, %1;" : "=r"(u) : "f"(x));
    return __uint_as_float(u);
}

__device__ __forceinline__ void mma_tf32(float* d, const float* a, const float* b) {
    asm volatile(
        "mma.sync.aligned.m16n8k8.row.col.f32.tf32.tf32.f32 "
        "{%0,%1,%2,%3}, {%4,%5,%6,%7}, {%8,%9}, {%0,%1,%2,%3};\n"
        : "+f"(d[0]), "+f"(d[1]), "+f"(d[2]), "+f"(d[3])
        : "r"(__float_as_uint(a[0])), "r"(__float_as_uint(a[1])),
          "r"(__float_as_uint(a[2])), "r"(__float_as_uint(a[3])),
          "r"(__float_as_uint(b[0])), "r"(__float_as_uint(b[1])));
}

template <int MODE>
__global__ __launch_bounds__(256, 2)
void gemm_tf32_kernel(const float* __restrict__ A, const float* __restrict__ B,
                      const float* __restrict__ bias, const float* __restrict__ Cadd,
                      float* __restrict__ C, int M, int K, int Nc) {
    __shared__ float As[128][36];   // [m][k], pad 4 -> conflict-free frag loads
    __shared__ float Bs[32][132];   // [k][n], pad 4

    const int tid = threadIdx.x;
    const int wid = tid >> 5;
    const int lane = tid & 31;
    const int gid = lane >> 2;    // 0..7
    const int tig = lane & 3;     // 0..3
    const int wm = wid & 3;       // 0..3 -> rows wm*32
    const int wn = wid >> 2;      // 0..1 -> cols wn*64
    const int m0 = blockIdx.y * 128;
    const int n0 = blockIdx.x * 128;

    float acc[2][8][4];
    #pragma unroll
    for (int i = 0; i < 2; i++)
        #pragma unroll
        for (int j = 0; j < 8; j++)
            #pragma unroll
            for (int q = 0; q < 4; q++) acc[i][j][q] = 0.f;

    for (int k0 = 0; k0 < K; k0 += 32) {
        // load A tile: 128 rows x 32 k = 1024 float4; 4 per thread
        #pragma unroll
        for (int i = 0; i < 4; i++) {
            int id = tid + i * 256;
            int r  = id >> 3;          // 0..127
            int c4 = id & 7;           // 0..7
            int gm = m0 + r;
            float4 av = make_float4(0.f, 0.f, 0.f, 0.f);
            if (gm < M)
                av = *(const float4*)(A + (size_t)gm * K + k0 + c4 * 4);
            av.x = f2tf32(av.x); av.y = f2tf32(av.y);
            av.z = f2tf32(av.z); av.w = f2tf32(av.w);
            *(float4*)&As[r][c4 * 4] = av;   // row stride 144B, 16B-aligned
        }
        // load B tile: 32 k x 128 n = 1024 float4; 4 per thread
        #pragma unroll
        for (int i = 0; i < 4; i++) {
            int id = tid + i * 256;
            int rb = id >> 5;          // 0..31
            int cb = id & 31;          // 0..31
            int gn = n0 + cb * 4;
            float4 bv = make_float4(0.f, 0.f, 0.f, 0.f);
            if (gn < Nc)
                bv = *(const float4*)(B + (size_t)(k0 + rb) * Nc + gn);
            bv.x = f2tf32(bv.x); bv.y = f2tf32(bv.y);
            bv.z = f2tf32(bv.z); bv.w = f2tf32(bv.w);
            *(float4*)&Bs[rb][cb * 4] = bv;  // row stride 528B, 16B-aligned
        }
        __syncthreads();

        #pragma unroll
        for (int kk = 0; kk < 32; kk += 8) {
            float afr[2][4];
            #pragma unroll
            for (int mt = 0; mt < 2; mt++) {
                int r = wm * 32 + mt * 16 + gid;
                afr[mt][0] = As[r    ][kk + tig];
                afr[mt][1] = As[r + 8][kk + tig];
                afr[mt][2] = As[r    ][kk + tig + 4];
                afr[mt][3] = As[r + 8][kk + tig + 4];
            }
            float bfr[8][2];
            #pragma unroll
            for (int nt = 0; nt < 8; nt++) {
                int cc = wn * 64 + nt * 8 + gid;
                bfr[nt][0] = Bs[kk + tig    ][cc];
                bfr[nt][1] = Bs[kk + tig + 4][cc];
            }
            #pragma unroll
            for (int mt = 0; mt < 2; mt++)
                #pragma unroll
                for (int nt = 0; nt < 8; nt++)
                    mma_tf32(acc[mt][nt], afr[mt], bfr[nt]);
        }
        __syncthreads();
    }

    // epilogue: c0,c1 at (row, col..col+1); c2,c3 at (row+8, col..col+1)
    #pragma unroll
    for (int mt = 0; mt < 2; mt++) {
        int r0 = m0 + wm * 32 + mt * 16 + gid;
        #pragma unroll
        for (int nt = 0; nt < 8; nt++) {
            int c = n0 + wn * 64 + nt * 8 + tig * 2;
            if (c >= Nc) continue;
            float bz0 = __ldg(&bias[c]);
            float bz1 = __ldg(&bias[c + 1]);
            if (r0 < M) {
                float v0 = acc[mt][nt][0] + bz0;
                float v1 = acc[mt][nt][1] + bz1;
                if (MODE == 1) {
                    const float* cp = Cadd + (size_t)r0 * Nc + c;
                    v0 += __ldg(cp); v1 += __ldg(cp + 1);
                }
                if (MODE != 2) { v0 = fmaxf(v0, 0.f); v1 = fmaxf(v1, 0.f); }
                float* op = C + (size_t)r0 * Nc + c;
                op[0] = v0; op[1] = v1;
            }
            int r1 = r0 + 8;
            if (r1 < M) {
                float v2 = acc[mt][nt][2] + bz0;
                float v3 = acc[mt][nt][3] + bz1;
                if (MODE == 1) {
                    const float* cp = Cadd + (size_t)r1 * Nc + c;
                    v2 += __ldg(cp); v3 += __ldg(cp + 1);
                }
                if (MODE != 2) { v2 = fmaxf(v2, 0.f); v3 = fmaxf(v3, 0.f); }
                float* op = C + (size_t)r1 * Nc + c;
                op[0] = v2; op[1] = v3;
            }
        }
    }
}

// ---------------- launch ----------------------------------------------------
extern "C" void kernel_launch(void* const* d_in, const int* in_sizes, int n_in,
                              void* d_out, int out_size) {
    const float* x    = (const float*)d_in[0];
    const int*   erow = (const int*)  d_in[1];
    const int*   ecol = (const int*)  d_in[2];
    const float* eval = (const float*)d_in[3];
    const float* A2   = (const float*)d_in[4];
    const float* W1   = (const float*)d_in[5];
    const float* b1   = (const float*)d_in[6];
    const float* W3   = (const float*)d_in[7];
    const float* b3   = (const float*)d_in[8];
    const float* W2   = (const float*)d_in[9];
    const float* b2   = (const float*)d_in[10];
    float* out = (float*)d_out;

    float *px0, *ptmp, *phA, *phB;
    cudaGetSymbolAddress((void**)&px0, g_x0);
    cudaGetSymbolAddress((void**)&ptmp, g_tmp);
    cudaGetSymbolAddress((void**)&phA, g_hA);
    cudaGetSymbolAddress((void**)&phB, g_hB);

    // ---- CSR build ----
    zero_cnt_kernel<<<(NN + 255) / 256, 256>>>();
    hist_kernel<<<(EE + 255) / 256, 256>>>(erow);
    scan_kernel<<<1, 1024>>>();
    zero_cnt_kernel<<<(NN + 255) / 256, 256>>>();
    scatter_kernel<<<(EE + 255) / 256, 256>>>(erow, ecol, eval);

    // ---- x0 = relu(x @ W1 + b1) ----
    dim3 grid1((FH + 127) / 128, (NN + 127) / 128);
    gemm_tf32_kernel<0><<<grid1, 256>>>(x, W1, b1, nullptr, px0, NN, FIN, FH);

    // ---- 10 hops ----
    const float* h = px0;
    float* bufs[2] = {phA, phB};
    for (int i = 0; i < HOPS; i++) {
        spmm_kernel<<<(NN + 3) / 4, 256>>>(h, A2);
        float* hn = bufs[i & 1];
        dim3 grid3((FH + 127) / 128, (NN + 127) / 128);
        gemm_tf32_kernel<1><<<grid3, 256>>>(ptmp, W3, b3, ptmp, hn, NN, FH, FH);
        h = hn;
    }

    // ---- out = h @ W2 + b2 ----
    dim3 grid2((FOUT + 127) / 128, (NN + 127) / 128);
    gemm_tf32_kernel<2><<<grid2, 256>>>(h, W2, b2, nullptr, out, NN, FH, FOUT);
}

// round 3
// speedup vs baseline: 2.0613x; 1.3725x over previous
#include <cuda_runtime.h>
#include <cuda_fp16.h>
#include <cstdint>

#define NN   100000
#define EE   3200000
#define FH   256
#define FIN  512
#define FOUT 64
#define HOPS 10

// ---------------- scratch (device globals: no allocations allowed) ----------
__device__ float  g_x0 [(size_t)NN * FH];   // fp32 residual x0
__device__ float  g_tmp[(size_t)NN * FH];   // fp32 spmm output
__device__ __half g_h16[(size_t)NN * FH];   // fp16 h (gather + A operand)
__device__ int    g_rowstart[NN + 1];
__device__ int    g_cnt[NN];
__device__ int2   g_epack[EE];              // {col, bits(val)}

// ---------------- CSR build ------------------------------------------------
__global__ void zero_cnt_kernel() {
    int i = blockIdx.x * blockDim.x + threadIdx.x;
    if (i < NN) g_cnt[i] = 0;
}

__global__ void hist_kernel(const int* __restrict__ erow) {
    int e = blockIdx.x * blockDim.x + threadIdx.x;
    if (e < EE) atomicAdd(&g_cnt[erow[e]], 1);
}

__global__ void scan_kernel() {
    __shared__ int s[1024];
    __shared__ int carry_s;
    int t = threadIdx.x;
    if (t == 0) carry_s = 0;
    __syncthreads();
    for (int base = 0; base < NN; base += 1024) {
        int i = base + t;
        int v = (i < NN) ? g_cnt[i] : 0;
        s[t] = v;
        __syncthreads();
        #pragma unroll
        for (int off = 1; off < 1024; off <<= 1) {
            int add = (t >= off) ? s[t - off] : 0;
            __syncthreads();
            s[t] += add;
            __syncthreads();
        }
        if (i < NN) g_rowstart[i] = carry_s + s[t] - v;
        __syncthreads();
        if (t == 1023) carry_s += s[1023];
        __syncthreads();
    }
    if (t == 0) g_rowstart[NN] = carry_s;
}

__global__ void scatter_kernel(const int* __restrict__ erow,
                               const int* __restrict__ ecol,
                               const float* __restrict__ eval) {
    int e = blockIdx.x * blockDim.x + threadIdx.x;
    if (e < EE) {
        int r = erow[e];
        int p = g_rowstart[r] + atomicAdd(&g_cnt[r], 1);
        g_epack[p] = make_int2(ecol[e], __float_as_int(eval[e]));
    }
}

// ---------------- SPMM: tmp[row,:] = sum val*h16[col,:] + A2[row]*x0[row,:]
// 32 threads per row (8 halves each), 8 rows per 256-thread block.
__global__ void spmm_kernel(const __half* __restrict__ h,
                            const float* __restrict__ A2) {
    int row  = blockIdx.x * 8 + (threadIdx.x >> 5);
    int lane = threadIdx.x & 31;
    if (row >= NN) return;
    int s = g_rowstart[row];
    int e = g_rowstart[row + 1];
    float acc[8];
    #pragma unroll
    for (int q = 0; q < 8; q++) acc[q] = 0.f;

    #pragma unroll 2
    for (int p = s; p < e; ++p) {
        int2 ev = __ldg(&g_epack[p]);
        float v = __int_as_float(ev.y);
        uint4 raw = __ldg(((const uint4*)(h + (size_t)ev.x * FH)) + lane);
        const __half2* hh = (const __half2*)&raw;
        #pragma unroll
        for (int q = 0; q < 4; q++) {
            float2 f = __half22float2(hh[q]);
            acc[2 * q]     += v * f.x;
            acc[2 * q + 1] += v * f.y;
        }
    }
    float a = __ldg(&A2[row]);
    const float4* xp = ((const float4*)(g_x0 + (size_t)row * FH)) + lane * 2;
    float4 xa = __ldg(xp);
    float4 xb = __ldg(xp + 1);
    acc[0] += a * xa.x; acc[1] += a * xa.y; acc[2] += a * xa.z; acc[3] += a * xa.w;
    acc[4] += a * xb.x; acc[5] += a * xb.y; acc[6] += a * xb.z; acc[7] += a * xb.w;
    float4* op = ((float4*)(g_tmp + (size_t)row * FH)) + lane * 2;
    op[0] = make_float4(acc[0], acc[1], acc[2], acc[3]);
    op[1] = make_float4(acc[4], acc[5], acc[6], acc[7]);
}

// ---------------- tf32 tensor-core GEMM ------------------------------------
// MODE 0: x0 = relu(acc+bias)  -> writes C fp32 AND H16 fp16   (A = float)
// MODE 1: h  = relu(acc+bias+Cadd) -> writes H16 fp16 only     (A = float)
// MODE 2: out = acc+bias       -> writes C fp32                (A = half)
__device__ __forceinline__ float f2tf32(float x) {
    uint32_t u;
    asm("cvt.rna.tf32.f32 %0, %1;" : "=r"(u) : "f"(x));
    return __uint_as_float(u);
}

__device__ __forceinline__ void mma_tf32(float* d, const float* a, const float* b) {
    asm volatile(
        "mma.sync.aligned.m16n8k8.row.col.f32.tf32.tf32.f32 "
        "{%0,%1,%2,%3}, {%4,%5,%6,%7}, {%8,%9}, {%0,%1,%2,%3};\n"
        : "+f"(d[0]), "+f"(d[1]), "+f"(d[2]), "+f"(d[3])
        : "r"(__float_as_uint(a[0])), "r"(__float_as_uint(a[1])),
          "r"(__float_as_uint(a[2])), "r"(__float_as_uint(a[3])),
          "r"(__float_as_uint(b[0])), "r"(__float_as_uint(b[1])));
}

template <int MODE, typename TA>
__global__ __launch_bounds__(256, 2)
void gemm_tc_kernel(const TA* __restrict__ A, const float* __restrict__ B,
                    const float* __restrict__ bias, const float* __restrict__ Cadd,
                    float* __restrict__ C, __half* __restrict__ H16,
                    int M, int K, int Nc) {
    __shared__ float As[128][36];
    __shared__ float Bs[32][132];

    const int tid = threadIdx.x;
    const int wid = tid >> 5;
    const int lane = tid & 31;
    const int gid = lane >> 2;
    const int tig = lane & 3;
    const int wm = wid & 3;
    const int wn = wid >> 2;
    const int m0 = blockIdx.y * 128;
    const int n0 = blockIdx.x * 128;

    float acc[2][8][4];
    #pragma unroll
    for (int i = 0; i < 2; i++)
        #pragma unroll
        for (int j = 0; j < 8; j++)
            #pragma unroll
            for (int q = 0; q < 4; q++) acc[i][j][q] = 0.f;

    for (int k0 = 0; k0 < K; k0 += 32) {
        // ---- load A tile (128 x 32) ----
        if (sizeof(TA) == 4) {
            const float* Af = (const float*)A;
            #pragma unroll
            for (int i = 0; i < 4; i++) {
                int id = tid + i * 256;
                int r  = id >> 3;
                int c4 = id & 7;
                int gm = m0 + r;
                float4 av = make_float4(0.f, 0.f, 0.f, 0.f);
                if (gm < M)
                    av = *(const float4*)(Af + (size_t)gm * K + k0 + c4 * 4);
                av.x = f2tf32(av.x); av.y = f2tf32(av.y);
                av.z = f2tf32(av.z); av.w = f2tf32(av.w);
                *(float4*)&As[r][c4 * 4] = av;
            }
        } else {
            const __half* Ah = (const __half*)A;
            #pragma unroll
            for (int i = 0; i < 2; i++) {
                int id = tid + i * 256;     // 0..511
                int r  = id >> 2;           // 0..127
                int g  = id & 3;            // k-group of 8
                int gm = m0 + r;
                uint4 av = make_uint4(0u, 0u, 0u, 0u);
                if (gm < M)
                    av = *(const uint4*)(Ah + (size_t)gm * K + k0 + g * 8);
                const __half2* hp = (const __half2*)&av;
                float2 f0 = __half22float2(hp[0]);
                float2 f1 = __half22float2(hp[1]);
                float2 f2 = __half22float2(hp[2]);
                float2 f3 = __half22float2(hp[3]);
                // fp16->fp32 is exact and fits tf32 mantissa: no cvt needed
                *(float4*)&As[r][g * 8]     = make_float4(f0.x, f0.y, f1.x, f1.y);
                *(float4*)&As[r][g * 8 + 4] = make_float4(f2.x, f2.y, f3.x, f3.y);
            }
        }
        // ---- load B tile (32 x 128) ----
        #pragma unroll
        for (int i = 0; i < 4; i++) {
            int id = tid + i * 256;
            int rb = id >> 5;
            int cb = id & 31;
            int gn = n0 + cb * 4;
            float4 bv = make_float4(0.f, 0.f, 0.f, 0.f);
            if (gn < Nc)
                bv = *(const float4*)(B + (size_t)(k0 + rb) * Nc + gn);
            bv.x = f2tf32(bv.x); bv.y = f2tf32(bv.y);
            bv.z = f2tf32(bv.z); bv.w = f2tf32(bv.w);
            *(float4*)&Bs[rb][cb * 4] = bv;
        }
        __syncthreads();

        #pragma unroll
        for (int kk = 0; kk < 32; kk += 8) {
            float afr[2][4];
            #pragma unroll
            for (int mt = 0; mt < 2; mt++) {
                int r = wm * 32 + mt * 16 + gid;
                afr[mt][0] = As[r    ][kk + tig];
                afr[mt][1] = As[r + 8][kk + tig];
                afr[mt][2] = As[r    ][kk + tig + 4];
                afr[mt][3] = As[r + 8][kk + tig + 4];
            }
            float bfr[8][2];
            #pragma unroll
            for (int nt = 0; nt < 8; nt++) {
                int cc = wn * 64 + nt * 8 + gid;
                bfr[nt][0] = Bs[kk + tig    ][cc];
                bfr[nt][1] = Bs[kk + tig + 4][cc];
            }
            #pragma unroll
            for (int mt = 0; mt < 2; mt++)
                #pragma unroll
                for (int nt = 0; nt < 8; nt++)
                    mma_tf32(acc[mt][nt], afr[mt], bfr[nt]);
        }
        __syncthreads();
    }

    // ---- epilogue ----
    #pragma unroll
    for (int mt = 0; mt < 2; mt++) {
        #pragma unroll
        for (int half_m = 0; half_m < 2; half_m++) {
            int r = m0 + wm * 32 + mt * 16 + half_m * 8 + gid;
            if (r >= M) continue;
            #pragma unroll
            for (int nt = 0; nt < 8; nt++) {
                int c = n0 + wn * 64 + nt * 8 + tig * 2;
                if (c >= Nc) continue;
                float v0 = acc[mt][nt][half_m * 2]     + __ldg(&bias[c]);
                float v1 = acc[mt][nt][half_m * 2 + 1] + __ldg(&bias[c + 1]);
                if (MODE == 1) {
                    const float* cp = Cadd + (size_t)r * Nc + c;
                    v0 += __ldg(cp); v1 += __ldg(cp + 1);
                }
                if (MODE != 2) { v0 = fmaxf(v0, 0.f); v1 = fmaxf(v1, 0.f); }
                if (MODE != 1) {
                    float* op = C + (size_t)r * Nc + c;
                    op[0] = v0; op[1] = v1;
                }
                if (MODE != 2) {
                    *(__half2*)(H16 + (size_t)r * Nc + c) =
                        __floats2half2_rn(v0, v1);
                }
            }
        }
    }
}

// ---------------- launch ----------------------------------------------------
extern "C" void kernel_launch(void* const* d_in, const int* in_sizes, int n_in,
                              void* d_out, int out_size) {
    const float* x    = (const float*)d_in[0];
    const int*   erow = (const int*)  d_in[1];
    const int*   ecol = (const int*)  d_in[2];
    const float* eval = (const float*)d_in[3];
    const float* A2   = (const float*)d_in[4];
    const float* W1   = (const float*)d_in[5];
    const float* b1   = (const float*)d_in[6];
    const float* W3   = (const float*)d_in[7];
    const float* b3   = (const float*)d_in[8];
    const float* W2   = (const float*)d_in[9];
    const float* b2   = (const float*)d_in[10];
    float* out = (float*)d_out;

    float  *px0, *ptmp;
    __half *ph16;
    cudaGetSymbolAddress((void**)&px0,  g_x0);
    cudaGetSymbolAddress((void**)&ptmp, g_tmp);
    cudaGetSymbolAddress((void**)&ph16, g_h16);

    // ---- CSR build ----
    zero_cnt_kernel<<<(NN + 255) / 256, 256>>>();
    hist_kernel<<<(EE + 255) / 256, 256>>>(erow);
    scan_kernel<<<1, 1024>>>();
    zero_cnt_kernel<<<(NN + 255) / 256, 256>>>();
    scatter_kernel<<<(EE + 255) / 256, 256>>>(erow, ecol, eval);

    // ---- x0 = relu(x @ W1 + b1)  (fp32 + fp16 copy) ----
    dim3 grid1((FH + 127) / 128, (NN + 127) / 128);
    gemm_tc_kernel<0, float><<<grid1, 256>>>(x, W1, b1, nullptr, px0, ph16,
                                             NN, FIN, FH);

    // ---- 10 hops: spmm(h16) -> tmp ; h16 = relu(tmp@W3 + b3 + tmp) ----
    dim3 grid3((FH + 127) / 128, (NN + 127) / 128);
    for (int i = 0; i < HOPS; i++) {
        spmm_kernel<<<(NN + 7) / 8, 256>>>(ph16, A2);
        gemm_tc_kernel<1, float><<<grid3, 256>>>(ptmp, W3, b3, ptmp,
                                                 nullptr, ph16, NN, FH, FH);
    }

    // ---- out = h16 @ W2 + b2 ----
    dim3 grid2((FOUT + 127) / 128, (NN + 127) / 128);
    gemm_tc_kernel<2, __half><<<grid2, 256>>>(ph16, W2, b2, nullptr, out,
                                              nullptr, NN, FH, FOUT);
}

// round 4
// speedup vs baseline: 3.0236x; 1.4668x over previous
#include <cuda_runtime.h>
#include <cuda_fp16.h>
#include <cstdint>

#define NN   100000
#define EE   3200000
#define FH   256
#define FIN  512
#define FOUT 64
#define HOPS 10

// ---------------- scratch (device globals) ----------------------------------
__device__ __half g_x16 [(size_t)NN * FIN];  // fp16 copy of input x
__device__ __half g_x016[(size_t)NN * FH];   // fp16 x0 (residual source)
__device__ __half g_h16 [(size_t)NN * FH];   // fp16 h
__device__ __half g_t16 [(size_t)NN * FH];   // fp16 spmm output (GEMM A operand)
__device__ __half g_W1t [(size_t)FIN * FH];  // [n][k] transposed fp16 weights
__device__ __half g_W3p [(size_t)FH * FH];   // (W3 + I)^T
__device__ __half g_W2t [(size_t)FH * FOUT];
__device__ int    g_rowstart[NN + 1];
__device__ int    g_cnt[NN];
__device__ int2   g_epack[EE];               // {col, bits(val)}

// ---------------- conversions ------------------------------------------------
__global__ void x2h_kernel(const float* __restrict__ x) {
    size_t i = (size_t)blockIdx.x * blockDim.x + threadIdx.x;   // per 8 elems
    if (i >= (size_t)NN * FIN / 8) return;
    float4 a = __ldg(((const float4*)x) + 2 * i);
    float4 b = __ldg(((const float4*)x) + 2 * i + 1);
    uint4 o;
    ((__half2*)&o)[0] = __floats2half2_rn(a.x, a.y);
    ((__half2*)&o)[1] = __floats2half2_rn(a.z, a.w);
    ((__half2*)&o)[2] = __floats2half2_rn(b.x, b.y);
    ((__half2*)&o)[3] = __floats2half2_rn(b.z, b.w);
    ((uint4*)g_x16)[i] = o;
}

// Bt[n*K + k] = W[k*Nc + n] (+ I)
__global__ void wt_kernel(const float* __restrict__ W, __half* __restrict__ Bt,
                          int K, int Nc, int addI) {
    int i = blockIdx.x * blockDim.x + threadIdx.x;
    if (i >= K * Nc) return;
    int n = i / K, k = i % K;
    float v = __ldg(&W[(size_t)k * Nc + n]);
    if (addI && k == n) v += 1.0f;
    Bt[i] = __float2half_rn(v);
}

// ---------------- CSR build --------------------------------------------------
__global__ void zero_cnt_kernel() {
    int i = blockIdx.x * blockDim.x + threadIdx.x;
    if (i < NN) g_cnt[i] = 0;
}

__global__ void hist_kernel(const int* __restrict__ erow) {
    int e = blockIdx.x * blockDim.x + threadIdx.x;
    if (e < EE) atomicAdd(&g_cnt[erow[e]], 1);
}

__global__ void scan_kernel() {
    __shared__ int wsum[32];
    __shared__ int carry_s;
    int t = threadIdx.x, lane = t & 31, w = t >> 5;
    if (t == 0) carry_s = 0;
    __syncthreads();
    for (int base = 0; base < NN; base += 1024) {
        int i = base + t;
        int v = (i < NN) ? g_cnt[i] : 0;
        int s = v;
        #pragma unroll
        for (int off = 1; off < 32; off <<= 1) {
            int u = __shfl_up_sync(0xffffffff, s, off);
            if (lane >= off) s += u;
        }
        if (lane == 31) wsum[w] = s;
        __syncthreads();
        if (w == 0) {
            int ws = (lane < 32) ? wsum[lane] : 0;
            #pragma unroll
            for (int off = 1; off < 32; off <<= 1) {
                int u = __shfl_up_sync(0xffffffff, ws, off);
                if (lane >= off) ws += u;
            }
            wsum[lane] = ws;
        }
        __syncthreads();
        int wpre = (w == 0) ? 0 : wsum[w - 1];
        if (i < NN) g_rowstart[i] = carry_s + wpre + s - v;   // exclusive
        __syncthreads();
        if (t == 1023) carry_s += wsum[31];
        __syncthreads();
    }
    if (threadIdx.x == 0) g_rowstart[NN] = carry_s;
}

__global__ void scatter_kernel(const int* __restrict__ erow,
                               const int* __restrict__ ecol,
                               const float* __restrict__ eval) {
    int e = blockIdx.x * blockDim.x + threadIdx.x;
    if (e < EE) {
        int r = erow[e];
        int p = g_rowstart[r] + atomicAdd(&g_cnt[r], 1);
        g_epack[p] = make_int2(ecol[e], __float_as_int(eval[e]));
    }
}

// ---------------- SPMM: t16[row,:] = sum val*h16[col,:] + A2[row]*x016[row,:]
__global__ void spmm_kernel(const __half* __restrict__ h,
                            const float* __restrict__ A2) {
    int row  = blockIdx.x * 8 + (threadIdx.x >> 5);
    int lane = threadIdx.x & 31;
    if (row >= NN) return;
    int s = g_rowstart[row];
    int e = g_rowstart[row + 1];
    float acc[8];
    #pragma unroll
    for (int q = 0; q < 8; q++) acc[q] = 0.f;

    #pragma unroll 2
    for (int p = s; p < e; ++p) {
        int2 ev = __ldg(&g_epack[p]);
        float v = __int_as_float(ev.y);
        uint4 raw = __ldg(((const uint4*)(h + (size_t)ev.x * FH)) + lane);
        const __half2* hh = (const __half2*)&raw;
        #pragma unroll
        for (int q = 0; q < 4; q++) {
            float2 f = __half22float2(hh[q]);
            acc[2 * q]     += v * f.x;
            acc[2 * q + 1] += v * f.y;
        }
    }
    float a = __ldg(&A2[row]);
    uint4 xraw = __ldg(((const uint4*)(g_x016 + (size_t)row * FH)) + lane);
    const __half2* xh = (const __half2*)&xraw;
    #pragma unroll
    for (int q = 0; q < 4; q++) {
        float2 f = __half22float2(xh[q]);
        acc[2 * q]     += a * f.x;
        acc[2 * q + 1] += a * f.y;
    }
    uint4 o;
    #pragma unroll
    for (int q = 0; q < 4; q++)
        ((__half2*)&o)[q] = __floats2half2_rn(acc[2 * q], acc[2 * q + 1]);
    ((uint4*)(g_t16 + (size_t)row * FH))[lane] = o;
}

// ---------------- fp16 tensor-core GEMM --------------------------------------
// C = epilogue(A[M,K] @ Bt[Nc,K]^T)
// MODE 0: relu(acc+bias) -> write fp16 to O1 AND O2
// MODE 1: relu(acc+bias) -> write fp16 to O1
// MODE 2: acc+bias       -> write fp32 to OF
__device__ __forceinline__ void mma_f16(float* d, const uint32_t* a, const uint32_t* b) {
    asm volatile(
        "mma.sync.aligned.m16n8k16.row.col.f32.f16.f16.f32 "
        "{%0,%1,%2,%3}, {%4,%5,%6,%7}, {%8,%9}, {%0,%1,%2,%3};\n"
        : "+f"(d[0]), "+f"(d[1]), "+f"(d[2]), "+f"(d[3])
        : "r"(a[0]), "r"(a[1]), "r"(a[2]), "r"(a[3]),
          "r"(b[0]), "r"(b[1]));
}

template <int MODE>
__global__ __launch_bounds__(256, 2)
void gemm_f16_kernel(const __half* __restrict__ A, const __half* __restrict__ Bt,
                     const float* __restrict__ bias, float* __restrict__ OF,
                     __half* __restrict__ O1, __half* __restrict__ O2,
                     int M, int K, int Nc) {
    __shared__ __half As[128][40];   // [m][k], pad 8 halves
    __shared__ __half Bs[128][40];   // [n][k], pad 8 halves

    const int tid = threadIdx.x;
    const int wid = tid >> 5;
    const int lane = tid & 31;
    const int gid = lane >> 2;   // 0..7
    const int tig = lane & 3;    // 0..3
    const int wm = wid & 3;      // rows wm*32
    const int wn = wid >> 2;     // cols wn*64
    const int m0 = blockIdx.y * 128;
    const int n0 = blockIdx.x * 128;

    float acc[2][8][4];
    #pragma unroll
    for (int i = 0; i < 2; i++)
        #pragma unroll
        for (int j = 0; j < 8; j++)
            #pragma unroll
            for (int q = 0; q < 4; q++) acc[i][j][q] = 0.f;

    for (int k0 = 0; k0 < K; k0 += 32) {
        // A tile: 128 rows x 32 halves = 512 uint4, 2 per thread
        #pragma unroll
        for (int i = 0; i < 2; i++) {
            int id = tid + i * 256;
            int r  = id >> 2;        // 0..127
            int g  = id & 3;         // 8-half group
            int gm = m0 + r;
            uint4 av = make_uint4(0u, 0u, 0u, 0u);
            if (gm < M)
                av = *(const uint4*)(A + (size_t)gm * K + k0 + g * 8);
            *(uint4*)&As[r][g * 8] = av;
        }
        // B tile: 128 n-rows x 32 halves of Bt
        #pragma unroll
        for (int i = 0; i < 2; i++) {
            int id = tid + i * 256;
            int r  = id >> 2;
            int g  = id & 3;
            int gn = n0 + r;
            uint4 bv = make_uint4(0u, 0u, 0u, 0u);
            if (gn < Nc)
                bv = *(const uint4*)(Bt + (size_t)gn * K + k0 + g * 8);
            *(uint4*)&Bs[r][g * 8] = bv;
        }
        __syncthreads();

        #pragma unroll
        for (int kk = 0; kk < 32; kk += 16) {
            uint32_t afr[2][4];
            #pragma unroll
            for (int mt = 0; mt < 2; mt++) {
                int r = wm * 32 + mt * 16 + gid;
                afr[mt][0] = *(const uint32_t*)&As[r    ][kk + tig * 2];
                afr[mt][1] = *(const uint32_t*)&As[r + 8][kk + tig * 2];
                afr[mt][2] = *(const uint32_t*)&As[r    ][kk + tig * 2 + 8];
                afr[mt][3] = *(const uint32_t*)&As[r + 8][kk + tig * 2 + 8];
            }
            uint32_t bfr[8][2];
            #pragma unroll
            for (int nt = 0; nt < 8; nt++) {
                int cc = wn * 64 + nt * 8 + gid;
                bfr[nt][0] = *(const uint32_t*)&Bs[cc][kk + tig * 2];
                bfr[nt][1] = *(const uint32_t*)&Bs[cc][kk + tig * 2 + 8];
            }
            #pragma unroll
            for (int mt = 0; mt < 2; mt++)
                #pragma unroll
                for (int nt = 0; nt < 8; nt++)
                    mma_f16(acc[mt][nt], afr[mt], bfr[nt]);
        }
        __syncthreads();
    }

    // epilogue
    #pragma unroll
    for (int mt = 0; mt < 2; mt++) {
        #pragma unroll
        for (int hm = 0; hm < 2; hm++) {
            int r = m0 + wm * 32 + mt * 16 + hm * 8 + gid;
            if (r >= M) continue;
            #pragma unroll
            for (int nt = 0; nt < 8; nt++) {
                int c = n0 + wn * 64 + nt * 8 + tig * 2;
                if (c >= Nc) continue;
                float v0 = acc[mt][nt][hm * 2]     + __ldg(&bias[c]);
                float v1 = acc[mt][nt][hm * 2 + 1] + __ldg(&bias[c + 1]);
                if (MODE != 2) {
                    v0 = fmaxf(v0, 0.f); v1 = fmaxf(v1, 0.f);
                    __half2 hv = __floats2half2_rn(v0, v1);
                    *(__half2*)(O1 + (size_t)r * Nc + c) = hv;
                    if (MODE == 0)
                        *(__half2*)(O2 + (size_t)r * Nc + c) = hv;
                } else {
                    float* op = OF + (size_t)r * Nc + c;
                    op[0] = v0; op[1] = v1;
                }
            }
        }
    }
}

// ---------------- launch ------------------------------------------------------
extern "C" void kernel_launch(void* const* d_in, const int* in_sizes, int n_in,
                              void* d_out, int out_size) {
    const float* x    = (const float*)d_in[0];
    const int*   erow = (const int*)  d_in[1];
    const int*   ecol = (const int*)  d_in[2];
    const float* eval = (const float*)d_in[3];
    const float* A2   = (const float*)d_in[4];
    const float* W1   = (const float*)d_in[5];
    const float* b1   = (const float*)d_in[6];
    const float* W3   = (const float*)d_in[7];
    const float* b3   = (const float*)d_in[8];
    const float* W2   = (const float*)d_in[9];
    const float* b2   = (const float*)d_in[10];
    float* out = (float*)d_out;

    __half *px16, *px016, *ph16, *pt16, *pW1t, *pW3p, *pW2t;
    cudaGetSymbolAddress((void**)&px16,  g_x16);
    cudaGetSymbolAddress((void**)&px016, g_x016);
    cudaGetSymbolAddress((void**)&ph16,  g_h16);
    cudaGetSymbolAddress((void**)&pt16,  g_t16);
    cudaGetSymbolAddress((void**)&pW1t,  g_W1t);
    cudaGetSymbolAddress((void**)&pW3p,  g_W3p);
    cudaGetSymbolAddress((void**)&pW2t,  g_W2t);

    // ---- conversions ----
    x2h_kernel<<<(int)(((size_t)NN * FIN / 8 + 255) / 256), 256>>>(x);
    wt_kernel<<<(FIN * FH + 255) / 256, 256>>>(W1, pW1t, FIN, FH, 0);
    wt_kernel<<<(FH * FH + 255) / 256, 256>>>(W3, pW3p, FH, FH, 1);
    wt_kernel<<<(FH * FOUT + 255) / 256, 256>>>(W2, pW2t, FH, FOUT, 0);

    // ---- CSR build ----
    zero_cnt_kernel<<<(NN + 255) / 256, 256>>>();
    hist_kernel<<<(EE + 255) / 256, 256>>>(erow);
    scan_kernel<<<1, 1024>>>();
    zero_cnt_kernel<<<(NN + 255) / 256, 256>>>();
    scatter_kernel<<<(EE + 255) / 256, 256>>>(erow, ecol, eval);

    // ---- x0 = relu(x @ W1 + b1) -> x016 and h16 ----
    dim3 grid1((FH + 127) / 128, (NN + 127) / 128);
    gemm_f16_kernel<0><<<grid1, 256>>>(px16, pW1t, b1, nullptr, ph16, px016,
                                       NN, FIN, FH);

    // ---- 10 hops: t16 = spmm(h16) + A2*x016 ; h16 = relu(t16 @ (W3+I) + b3) ----
    dim3 grid3((FH + 127) / 128, (NN + 127) / 128);
    for (int i = 0; i < HOPS; i++) {
        spmm_kernel<<<(NN + 7) / 8, 256>>>(ph16, A2);
        gemm_f16_kernel<1><<<grid3, 256>>>(pt16, pW3p, b3, nullptr, ph16,
                                           nullptr, NN, FH, FH);
    }

    // ---- out = h16 @ W2 + b2 ----
    dim3 grid2((FOUT + 127) / 128, (NN + 127) / 128);
    gemm_f16_kernel<2><<<grid2, 256>>>(ph16, pW2t, b2, out, nullptr,
                                       nullptr, NN, FH, FOUT);
}